// round 5
// baseline (speedup 1.0000x reference)
#include <cuda_runtime.h>

// Problem constants (shapes fixed by the dataset)
#define NMAX 100000
#define EMAX 1000000
constexpr int GG   = 1024;
constexpr int FF   = 44;
constexpr int LD44 = 48;   // padded stride for width-44 buffers (192B, sector aligned)
constexpr int FEAT = 1019;

// ---------------- scratch (no allocations allowed) ----------------
__device__ int   g_cnt[NMAX];        // in-degree histogram (dst, excl. self-loop)
__device__ int   g_rowptr[NMAX + 1]; // CSR row offsets
__device__ int   g_cur[NMAX];        // scatter cursors
__device__ float g_dinv[NMAX];       // D^{-1/2}
__device__ int   g_csrc[EMAX];       // CSR column (src node)
__device__ float g_cw[EMAX];         // CSR edge weight dinv[s]*dinv[d]
__device__ float g_bufA[(size_t)NMAX * 88];    // width-88 intermediate (coalesced only)
__device__ float g_bufB[(size_t)NMAX * LD44];  // width-44, padded stride
__device__ float g_bufC[(size_t)NMAX * LD44];  // width-44, padded stride
__device__ float g_pool[GG * FF];    // max-pooled features (>=0)

// ---------------- init ----------------
__global__ void init_k(int n) {
    int i = blockIdx.x * blockDim.x + threadIdx.x;
    if (i < n) { g_cnt[i] = 0; g_cur[i] = 0; }
    if (i < GG * FF) g_pool[i] = 0.0f;
}

// ---------------- degree histogram over dst ----------------
__global__ void hist_k(const int* __restrict__ ei, int E) {
    int e = blockIdx.x * blockDim.x + threadIdx.x;
    if (e < E) atomicAdd(&g_cnt[ei[E + e]], 1);
}

// ---------------- single-block exclusive scan + dinv (N = 100K) ----------
__global__ void scan_k(int n) {
    __shared__ int s[1024];
    int t = threadIdx.x;
    int ch = (n + 1023) >> 10;
    int b0 = t * ch;
    int b1 = min(n, b0 + ch);
    int sum = 0;
    for (int i = b0; i < b1; i++) {
        int c = g_cnt[i];
        g_dinv[i] = rsqrtf((float)(c + 1));  // +1 self-loop (fused dinv)
        sum += c;
    }
    s[t] = sum;
    __syncthreads();
    for (int off = 1; off < 1024; off <<= 1) {
        int v = (t >= off) ? s[t - off] : 0;
        __syncthreads();
        s[t] += v;
        __syncthreads();
    }
    int excl = s[t] - sum;  // exclusive prefix of this chunk
    for (int i = b0; i < b1; i++) { g_rowptr[i] = excl; excl += g_cnt[i]; }
    if (t == 1023) g_rowptr[n] = s[1023];
}

// ---------------- scatter edges into CSR ----------------
__global__ void scatter_k(const int* __restrict__ ei, int E) {
    int e = blockIdx.x * blockDim.x + threadIdx.x;
    if (e >= E) return;
    int s = ei[e];
    int d = ei[E + e];
    int p = atomicAdd(&g_cur[d], 1);
    int idx = g_rowptr[d] + p;
    g_csrc[idx] = s;
    g_cw[idx] = g_dinv[s] * g_dinv[d];
}

// ---------------- dense GEMM: warp per node, W in smem ----------------
// Optional fused bias + ReLU epilogue (BR). Runtime leading dims.
template <int FIN, int FOUT, bool BR>
__global__ void gemm_k(const float* __restrict__ h, int ldi,
                       const float* __restrict__ W, const float* __restrict__ b,
                       float* __restrict__ out, int ldo, int n) {
    constexpr int NJ = (FOUT + 31) / 32;
    constexpr int NI = (FIN + 31) / 32;
    __shared__ float Ws[FIN * FOUT];
    for (int i = threadIdx.x; i < FIN * FOUT; i += blockDim.x) Ws[i] = W[i];
    __syncthreads();
    int warp = (int)((blockIdx.x * blockDim.x + threadIdx.x) >> 5);
    int lane = threadIdx.x & 31;
    if (warp >= n) return;
    float hr[NI];
#pragma unroll
    for (int c = 0; c < NI; c++) {
        int k = lane + 32 * c;
        hr[c] = (k < FIN) ? h[(size_t)warp * ldi + k] : 0.0f;
    }
    float acc[NJ];
#pragma unroll
    for (int c = 0; c < NJ; c++) acc[c] = 0.0f;
#pragma unroll
    for (int k = 0; k < FIN; k++) {
        float hk = __shfl_sync(0xffffffffu, hr[k >> 5], k & 31);
#pragma unroll
        for (int c = 0; c < NJ; c++) {
            int f = lane + 32 * c;
            if (f < FOUT) acc[c] += hk * Ws[k * FOUT + f];
        }
    }
#pragma unroll
    for (int c = 0; c < NJ; c++) {
        int f = lane + 32 * c;
        if (f < FOUT) {
            float v = acc[c];
            if (BR) {
                v += __ldg(&b[f]);
                v = v > 0.0f ? v : 0.0f;
            }
            out[(size_t)warp * ldo + f] = v;
        }
    }
}

// ---------------- SpMM core: warp computes one dst row (width 44) --------
// Pull mode over CSR, no float atomics. Returns acc in (acc0, acc1):
// lane holds features [lane] and [lane+32] (the latter valid for lane<12).
__device__ __forceinline__ void spmm_row(const float* __restrict__ hw, int node,
                                         int lane, float& acc0, float& acc1) {
    float dii = g_dinv[node];
    float sw = dii * dii;
    int f1 = lane + 32;
    bool two = f1 < FF;
    acc0 = hw[(size_t)node * LD44 + lane] * sw;                 // self-loop
    acc1 = two ? hw[(size_t)node * LD44 + f1] * sw : 0.0f;
    int beg = g_rowptr[node];
    int end = g_rowptr[node + 1];
    for (int base = beg; base < end; base += 32) {
        int e = base + lane;
        int s = 0;
        float w = 0.0f;
        if (e < end) { s = g_csrc[e]; w = g_cw[e]; }
        int m = end - base;  // uniform across warp
#pragma unroll
        for (int j = 0; j < 32; j++) {
            if (j < m) {
                int ss = __shfl_sync(0xffffffffu, s, j);
                float ww = __shfl_sync(0xffffffffu, w, j);
                const float* row = hw + (size_t)ss * LD44;
                acc0 += ww * row[lane];
                if (two) acc1 += ww * row[f1];
            }
        }
    }
}

// ---------------- standalone SpMM (optional bias+ReLU) ----------------
template <bool BR>
__global__ void spmm_k(const float* __restrict__ hw, const float* __restrict__ b,
                       float* __restrict__ out, int n) {
    int warp = (int)((blockIdx.x * blockDim.x + threadIdx.x) >> 5);
    int lane = threadIdx.x & 31;
    if (warp >= n) return;
    float acc0, acc1;
    spmm_row(hw, warp, lane, acc0, acc1);
    int f1 = lane + 32;
    bool two = f1 < FF;
    if (BR) {
        acc0 += __ldg(&b[lane]);
        acc0 = acc0 > 0.0f ? acc0 : 0.0f;
        if (two) {
            acc1 += __ldg(&b[f1]);
            acc1 = acc1 > 0.0f ? acc1 : 0.0f;
        }
    }
    out[(size_t)warp * LD44 + lane] = acc0;
    if (two) out[(size_t)warp * LD44 + f1] = acc1;
}

// ---------------- layer-2: SpMM fused with 44->88 GEMM (+bias, ReLU) -----
// The aggregated row stays in registers (acc0/acc1) and feeds the warp-GEMM
// via shuffle broadcast. Eliminates one 19.2MB intermediate round-trip.
__global__ void spmm_gemm_k(const float* __restrict__ hw,
                            const float* __restrict__ W,  // [44, 88]
                            const float* __restrict__ b,  // [88]
                            float* __restrict__ out, int n) {
    constexpr int FIN = 44, FOUT = 88;
    __shared__ float Ws[FIN * FOUT];
    for (int i = threadIdx.x; i < FIN * FOUT; i += blockDim.x) Ws[i] = W[i];
    __syncthreads();
    int warp = (int)((blockIdx.x * blockDim.x + threadIdx.x) >> 5);
    int lane = threadIdx.x & 31;
    if (warp >= n) return;
    float h0, h1;
    spmm_row(hw, warp, lane, h0, h1);  // aggregated input row, in registers
    float o0 = 0.0f, o1 = 0.0f, o2 = 0.0f;  // f = lane, lane+32, lane+64
    bool t2 = lane + 64 < FOUT;  // lanes 0..23
#pragma unroll
    for (int k = 0; k < FIN; k++) {
        float hk = __shfl_sync(0xffffffffu, (k < 32) ? h0 : h1, k & 31);
        const float* wr = Ws + k * FOUT;
        o0 += hk * wr[lane];
        o1 += hk * wr[lane + 32];
        if (t2) o2 += hk * wr[lane + 64];
    }
    float* orow = out + (size_t)warp * FOUT;
    o0 += __ldg(&b[lane]);
    orow[lane] = o0 > 0.0f ? o0 : 0.0f;
    o1 += __ldg(&b[lane + 32]);
    orow[lane + 32] = o1 > 0.0f ? o1 : 0.0f;
    if (t2) {
        o2 += __ldg(&b[lane + 64]);
        orow[lane + 64] = o2 > 0.0f ? o2 : 0.0f;
    }
}

// ---------------- layer-3 SpMM fused with global max pool ----------------
// 8 warps/block = 8 consecutive nodes; bias+ReLU applied; block-level max
// reduction in smem, then atomicMax per graph-run (batch sorted, so
// typically one run per block). Values >= 0: int-bits atomicMax onto the
// 0-initialized pool is exact.
__global__ void spmm_pool_k(const float* __restrict__ hw, const float* __restrict__ b,
                            const int* __restrict__ batch, int n) {
    __shared__ float srow[8][48];
    __shared__ int sgid[8];
    int wid = threadIdx.x >> 5;
    int lane = threadIdx.x & 31;
    int node = blockIdx.x * 8 + wid;
    if (node < n) {
        float acc0, acc1;
        spmm_row(hw, node, lane, acc0, acc1);
        acc0 += __ldg(&b[lane]);
        acc0 = acc0 > 0.0f ? acc0 : 0.0f;
        srow[wid][lane] = acc0;
        int f1 = lane + 32;
        if (f1 < 48) {
            if (f1 < FF) {
                acc1 += __ldg(&b[f1]);
                acc1 = acc1 > 0.0f ? acc1 : 0.0f;
                srow[wid][f1] = acc1;
            } else {
                srow[wid][f1] = 0.0f;
            }
        }
        if (lane == 0) sgid[wid] = batch[node];
    } else {
        if (lane == 0) sgid[wid] = -1;
    }
    __syncthreads();
    int t = threadIdx.x;
    if (t < FF) {
        float m = 0.0f;
        int curg = -1;
#pragma unroll
        for (int w = 0; w < 8; w++) {
            int g = sgid[w];
            if (g < 0) continue;
            if (g != curg) {
                if (curg >= 0) atomicMax((int*)&g_pool[curg * FF + t], __float_as_int(m));
                m = 0.0f;
                curg = g;
            }
            m = fmaxf(m, srow[w][t]);
        }
        if (curg >= 0) atomicMax((int*)&g_pool[curg * FF + t], __float_as_int(m));
    }
}

// ---------------- fused head: x1 + x2 per graph ----------------
// 8 graphs per block, 128 threads (one hidden unit each)
__global__ void final_k(const float* __restrict__ feat, const float* __restrict__ Wf1,
                        const float* __restrict__ bf1, const float* __restrict__ Wf2,
                        const float* __restrict__ bf2, const float* __restrict__ Wg,
                        const float* __restrict__ bg, float* __restrict__ out) {
    constexpr int GPB = 8;
    __shared__ float fsh[GPB][FEAT];
    __shared__ float red[GPB][128];
    int g0 = blockIdx.x * GPB;
    int t = threadIdx.x;
#pragma unroll
    for (int g = 0; g < GPB; g++)
        for (int k = t; k < FEAT; k += 128)
            fsh[g][k] = feat[(size_t)(g0 + g) * FEAT + k];
    __syncthreads();
    float acc[GPB];
    float bb = bf1[t];
#pragma unroll
    for (int g = 0; g < GPB; g++) acc[g] = bb;
#pragma unroll 4
    for (int k = 0; k < FEAT; k++) {
        float w = Wf1[k * 128 + t];
#pragma unroll
        for (int g = 0; g < GPB; g++) acc[g] += fsh[g][k] * w;
    }
    float w2 = Wf2[t];
#pragma unroll
    for (int g = 0; g < GPB; g++) red[g][t] = (acc[g] > 0.0f ? acc[g] : 0.0f) * w2;
    __syncthreads();
    for (int sft = 64; sft >= 1; sft >>= 1) {
        if (t < sft) {
#pragma unroll
            for (int g = 0; g < GPB; g++) red[g][t] += red[g][t + sft];
        }
        __syncthreads();
    }
    if (t < GPB) {
        int g = g0 + t;
        float x1 = bg[0];
        for (int k = 0; k < FF; k++) x1 += g_pool[g * FF + k] * Wg[k];
        x1 = x1 > 0.0f ? x1 : 0.0f;
        out[g] = x1 + red[t][0] + bf2[0];
    }
}

// ---------------- launch ----------------
extern "C" void kernel_launch(void* const* d_in, const int* in_sizes, int n_in,
                              void* d_out, int out_size) {
    const float* x       = (const float*)d_in[0];
    const int*   ei      = (const int*)d_in[1];
    const int*   batch   = (const int*)d_in[2];
    const float* feature = (const float*)d_in[3];
    const float* W1 = (const float*)d_in[4];
    const float* b1 = (const float*)d_in[5];
    const float* W2 = (const float*)d_in[6];
    const float* b2 = (const float*)d_in[7];
    const float* W3 = (const float*)d_in[8];
    const float* b3 = (const float*)d_in[9];
    const float* Wg = (const float*)d_in[10];
    const float* bg = (const float*)d_in[11];
    const float* Wf1 = (const float*)d_in[12];
    const float* bf1 = (const float*)d_in[13];
    const float* Wf2 = (const float*)d_in[14];
    const float* bf2 = (const float*)d_in[15];
    float* out = (float*)d_out;

    int N = in_sizes[0] / FF;
    int E = in_sizes[1] / 2;
    if (N > NMAX) N = NMAX;
    if (E > EMAX) E = EMAX;

    const int T = 256;
    int nb_N = (N + T - 1) / T;
    int nb_E = (E + T - 1) / T;
    int nb_W = (N * 32 + T - 1) / T;   // warp-per-node kernels (8 nodes/block)

    init_k<<<nb_N, T>>>(N);
    hist_k<<<nb_E, T>>>(ei, E);
    scan_k<<<1, 1024>>>(N);            // also computes g_dinv
    scatter_k<<<nb_E, T>>>(ei, E);

    // Layer 1 (44->44): transform, then aggregate (+b1, ReLU)
    gemm_k<44, 44, false><<<nb_W, T>>>(x, FF, W1, nullptr, g_bufC, LD44, N);
    spmm_k<true><<<nb_W, T>>>(g_bufC, b1, g_bufB, N);
    // Layer 2 (44->88): aggregate at width 44 fused with transform (+b2, ReLU)
    //   S(h W2) == (S h) W2  -- aggregate stays narrow AND in registers
    spmm_gemm_k<<<nb_W, T>>>(g_bufB, W2, b2, g_bufA, N);
    // Layer 3 (88->44): transform first (narrower output), then aggregate
    // fused with global max pooling (+b3, ReLU inside)
    gemm_k<88, 44, false><<<nb_W, T>>>(g_bufA, 88, W3, nullptr, g_bufC, LD44, N);
    spmm_pool_k<<<nb_W, T>>>(g_bufC, b3, batch, N);

    final_k<<<GG / 8, 128>>>(feature, Wf1, bf1, Wf2, bf2, Wg, bg, out);
}

// round 7
// speedup vs baseline: 1.3943x; 1.3943x over previous
#include <cuda_runtime.h>

// Problem constants (shapes fixed by the dataset)
#define NMAX 100000
#define EMAX 1000000
constexpr int GG   = 1024;
constexpr int FF   = 44;
constexpr int LD44 = 48;   // padded stride for width-44 buffers (192B, sector aligned)
constexpr int FEAT = 1019;

// ---------------- scratch (no allocations allowed) ----------------
// NOTE on replay determinism: statics start zeroed at module load. scan_k
// re-zeroes g_cnt/g_cur/g_pool every replay BEFORE their consumers run, and
// hist_k relies on g_cnt being zeroed by the PREVIOUS replay's scan_k (or
// module load on the first call). Every replay therefore sees identical state.
__device__ int   g_cnt[NMAX];        // in-degree histogram (dst, excl. self-loop)
__device__ int   g_rowptr[NMAX + 1]; // CSR row offsets
__device__ int   g_cur[NMAX];        // scatter cursors
__device__ float g_dinv[NMAX];       // D^{-1/2}
__device__ int   g_csrc[EMAX];       // CSR column (src node)
__device__ float g_cw[EMAX];         // CSR edge weight dinv[s]*dinv[d]
__device__ float g_bufA[(size_t)NMAX * 88];    // width-88 intermediate (coalesced only)
__device__ float g_bufB[(size_t)NMAX * LD44];  // width-44, padded stride
__device__ float g_bufC[(size_t)NMAX * LD44];  // width-44, padded stride
__device__ float g_pool[GG * FF];    // max-pooled features (>=0)

// ---------------- degree histogram over dst ----------------
// g_cnt is all-zero here: zeroed by previous replay's scan_k (or module load).
__global__ void hist_k(const int* __restrict__ ei, int E) {
    int e = blockIdx.x * blockDim.x + threadIdx.x;
    if (e < E) atomicAdd(&g_cnt[ei[E + e]], 1);
}

// ---------------- single-block scan + dinv + scratch zeroing -------------
__global__ void scan_k(int n) {
    __shared__ int s[1024];
    int t = threadIdx.x;
    int ch = (n + 1023) >> 10;
    int b0 = t * ch;
    int b1 = min(n, b0 + ch);
    int sum = 0;
    for (int i = b0; i < b1; i++) {
        int c = g_cnt[i];
        g_dinv[i] = rsqrtf((float)(c + 1));  // +1 self-loop (fused dinv)
        g_cur[i] = 0;                        // reset scatter cursors for this replay
        sum += c;
    }
    s[t] = sum;
    __syncthreads();
    for (int off = 1; off < 1024; off <<= 1) {
        int v = (t >= off) ? s[t - off] : 0;
        __syncthreads();
        s[t] += v;
        __syncthreads();
    }
    int excl = s[t] - sum;  // exclusive prefix of this chunk
    for (int i = b0; i < b1; i++) {
        g_rowptr[i] = excl;
        excl += g_cnt[i];
        g_cnt[i] = 0;       // leave zeroed for the NEXT replay's hist_k
    }
    if (t == 1023) g_rowptr[n] = s[1023];
    // zero the pool for this replay's spmm_pool_k (runs much later)
    for (int i = t; i < GG * FF; i += 1024) g_pool[i] = 0.0f;
}

// ---------------- scatter edges into CSR ----------------
__global__ void scatter_k(const int* __restrict__ ei, int E) {
    int e = blockIdx.x * blockDim.x + threadIdx.x;
    if (e >= E) return;
    int s = ei[e];
    int d = ei[E + e];
    int p = atomicAdd(&g_cur[d], 1);
    int idx = g_rowptr[d] + p;
    g_csrc[idx] = s;
    g_cw[idx] = g_dinv[s] * g_dinv[d];
}

// ---------------- dense GEMM: warp per node, W in smem ----------------
// Optional fused bias + ReLU epilogue (BR). Runtime leading dims.
template <int FIN, int FOUT, bool BR>
__global__ void gemm_k(const float* __restrict__ h, int ldi,
                       const float* __restrict__ W, const float* __restrict__ b,
                       float* __restrict__ out, int ldo, int n) {
    constexpr int NJ = (FOUT + 31) / 32;
    constexpr int NI = (FIN + 31) / 32;
    __shared__ float Ws[FIN * FOUT];
    for (int i = threadIdx.x; i < FIN * FOUT; i += blockDim.x) Ws[i] = W[i];
    __syncthreads();
    int warp = (int)((blockIdx.x * blockDim.x + threadIdx.x) >> 5);
    int lane = threadIdx.x & 31;
    if (warp >= n) return;
    float hr[NI];
#pragma unroll
    for (int c = 0; c < NI; c++) {
        int k = lane + 32 * c;
        hr[c] = (k < FIN) ? h[(size_t)warp * ldi + k] : 0.0f;
    }
    float acc[NJ];
#pragma unroll
    for (int c = 0; c < NJ; c++) acc[c] = 0.0f;
#pragma unroll
    for (int k = 0; k < FIN; k++) {
        float hk = __shfl_sync(0xffffffffu, hr[k >> 5], k & 31);
#pragma unroll
        for (int c = 0; c < NJ; c++) {
            int f = lane + 32 * c;
            if (f < FOUT) acc[c] += hk * Ws[k * FOUT + f];
        }
    }
#pragma unroll
    for (int c = 0; c < NJ; c++) {
        int f = lane + 32 * c;
        if (f < FOUT) {
            float v = acc[c];
            if (BR) {
                v += __ldg(&b[f]);
                v = v > 0.0f ? v : 0.0f;
            }
            out[(size_t)warp * ldo + f] = v;
        }
    }
}

// ---------------- SpMM core: warp computes one dst row (width 44) --------
// Pull mode over CSR, no float atomics. Input row stride LDI (44 for raw x,
// LD44 for padded buffers). lane holds features [lane] and [lane+32].
template <int LDI>
__device__ __forceinline__ void spmm_row(const float* __restrict__ hw, int node,
                                         int lane, float& acc0, float& acc1) {
    float dii = g_dinv[node];
    float sw = dii * dii;
    int f1 = lane + 32;
    bool two = f1 < FF;
    acc0 = hw[(size_t)node * LDI + lane] * sw;                  // self-loop
    acc1 = two ? hw[(size_t)node * LDI + f1] * sw : 0.0f;
    int beg = g_rowptr[node];
    int end = g_rowptr[node + 1];
    for (int base = beg; base < end; base += 32) {
        int e = base + lane;
        int s = 0;
        float w = 0.0f;
        if (e < end) { s = g_csrc[e]; w = g_cw[e]; }
        int m = end - base;  // uniform across warp
#pragma unroll
        for (int j = 0; j < 32; j++) {
            if (j < m) {
                int ss = __shfl_sync(0xffffffffu, s, j);
                float ww = __shfl_sync(0xffffffffu, w, j);
                const float* row = hw + (size_t)ss * LDI;
                acc0 += ww * row[lane];
                if (two) acc1 += ww * row[f1];
            }
        }
    }
}

// ---------------- standalone SpMM (optional bias+ReLU) ----------------
// Writes at padded stride LD44.
template <int LDI, bool BR>
__global__ void spmm_k(const float* __restrict__ hw, const float* __restrict__ b,
                       float* __restrict__ out, int n) {
    int warp = (int)((blockIdx.x * blockDim.x + threadIdx.x) >> 5);
    int lane = threadIdx.x & 31;
    if (warp >= n) return;
    float acc0, acc1;
    spmm_row<LDI>(hw, warp, lane, acc0, acc1);
    int f1 = lane + 32;
    bool two = f1 < FF;
    if (BR) {
        acc0 += __ldg(&b[lane]);
        acc0 = acc0 > 0.0f ? acc0 : 0.0f;
        if (two) {
            acc1 += __ldg(&b[f1]);
            acc1 = acc1 > 0.0f ? acc1 : 0.0f;
        }
    }
    out[(size_t)warp * LD44 + lane] = acc0;
    if (two) out[(size_t)warp * LD44 + f1] = acc1;
}

// ---------------- layer-2: SpMM fused with 44->88 GEMM (+bias, ReLU) -----
// The aggregated row stays in registers and feeds the warp-GEMM via shuffle
// broadcast. Eliminates one 19.2MB intermediate round-trip.
__global__ void spmm_gemm_k(const float* __restrict__ hw,
                            const float* __restrict__ W,  // [44, 88]
                            const float* __restrict__ b,  // [88]
                            float* __restrict__ out, int n) {
    constexpr int FIN = 44, FOUT = 88;
    __shared__ float Ws[FIN * FOUT];
    for (int i = threadIdx.x; i < FIN * FOUT; i += blockDim.x) Ws[i] = W[i];
    __syncthreads();
    int warp = (int)((blockIdx.x * blockDim.x + threadIdx.x) >> 5);
    int lane = threadIdx.x & 31;
    if (warp >= n) return;
    float h0, h1;
    spmm_row<LD44>(hw, warp, lane, h0, h1);  // aggregated input row, in registers
    float o0 = 0.0f, o1 = 0.0f, o2 = 0.0f;  // f = lane, lane+32, lane+64
    bool t2 = lane + 64 < FOUT;  // lanes 0..23
#pragma unroll
    for (int k = 0; k < FIN; k++) {
        float hk = __shfl_sync(0xffffffffu, (k < 32) ? h0 : h1, k & 31);
        const float* wr = Ws + k * FOUT;
        o0 += hk * wr[lane];
        o1 += hk * wr[lane + 32];
        if (t2) o2 += hk * wr[lane + 64];
    }
    float* orow = out + (size_t)warp * FOUT;
    o0 += __ldg(&b[lane]);
    orow[lane] = o0 > 0.0f ? o0 : 0.0f;
    o1 += __ldg(&b[lane + 32]);
    orow[lane + 32] = o1 > 0.0f ? o1 : 0.0f;
    if (t2) {
        o2 += __ldg(&b[lane + 64]);
        orow[lane + 64] = o2 > 0.0f ? o2 : 0.0f;
    }
}

// ---------------- layer-3 SpMM fused with global max pool ----------------
// 8 warps/block = 8 consecutive nodes; bias+ReLU applied; block-level max
// reduction in smem, then atomicMax per graph-run (batch sorted). Values
// >= 0: int-bits atomicMax onto the 0-initialized pool is exact.
__global__ void spmm_pool_k(const float* __restrict__ hw, const float* __restrict__ b,
                            const int* __restrict__ batch, int n) {
    __shared__ float srow[8][48];
    __shared__ int sgid[8];
    int wid = threadIdx.x >> 5;
    int lane = threadIdx.x & 31;
    int node = blockIdx.x * 8 + wid;
    if (node < n) {
        float acc0, acc1;
        spmm_row<LD44>(hw, node, lane, acc0, acc1);
        acc0 += __ldg(&b[lane]);
        acc0 = acc0 > 0.0f ? acc0 : 0.0f;
        srow[wid][lane] = acc0;
        int f1 = lane + 32;
        if (f1 < 48) {
            if (f1 < FF) {
                acc1 += __ldg(&b[f1]);
                acc1 = acc1 > 0.0f ? acc1 : 0.0f;
                srow[wid][f1] = acc1;
            } else {
                srow[wid][f1] = 0.0f;
            }
        }
        if (lane == 0) sgid[wid] = batch[node];
    } else {
        if (lane == 0) sgid[wid] = -1;
    }
    __syncthreads();
    int t = threadIdx.x;
    if (t < FF) {
        float m = 0.0f;
        int curg = -1;
#pragma unroll
        for (int w = 0; w < 8; w++) {
            int g = sgid[w];
            if (g < 0) continue;
            if (g != curg) {
                if (curg >= 0) atomicMax((int*)&g_pool[curg * FF + t], __float_as_int(m));
                m = 0.0f;
                curg = g;
            }
            m = fmaxf(m, srow[w][t]);
        }
        if (curg >= 0) atomicMax((int*)&g_pool[curg * FF + t], __float_as_int(m));
    }
}

// ---------------- fused head: x1 + x2 per graph ----------------
// 8 graphs per block, 128 threads (one hidden unit each)
__global__ void final_k(const float* __restrict__ feat, const float* __restrict__ Wf1,
                        const float* __restrict__ bf1, const float* __restrict__ Wf2,
                        const float* __restrict__ bf2, const float* __restrict__ Wg,
                        const float* __restrict__ bg, float* __restrict__ out) {
    constexpr int GPB = 8;
    __shared__ float fsh[GPB][FEAT];
    __shared__ float red[GPB][128];
    int g0 = blockIdx.x * GPB;
    int t = threadIdx.x;
#pragma unroll
    for (int g = 0; g < GPB; g++)
        for (int k = t; k < FEAT; k += 128)
            fsh[g][k] = feat[(size_t)(g0 + g) * FEAT + k];
    __syncthreads();
    float acc[GPB];
    float bb = bf1[t];
#pragma unroll
    for (int g = 0; g < GPB; g++) acc[g] = bb;
#pragma unroll 4
    for (int k = 0; k < FEAT; k++) {
        float w = Wf1[k * 128 + t];
#pragma unroll
        for (int g = 0; g < GPB; g++) acc[g] += fsh[g][k] * w;
    }
    float w2 = Wf2[t];
#pragma unroll
    for (int g = 0; g < GPB; g++) red[g][t] = (acc[g] > 0.0f ? acc[g] : 0.0f) * w2;
    __syncthreads();
    for (int sft = 64; sft >= 1; sft >>= 1) {
        if (t < sft) {
#pragma unroll
            for (int g = 0; g < GPB; g++) red[g][t] += red[g][t + sft];
        }
        __syncthreads();
    }
    if (t < GPB) {
        int g = g0 + t;
        float x1 = bg[0];
        for (int k = 0; k < FF; k++) x1 += g_pool[g * FF + k] * Wg[k];
        x1 = x1 > 0.0f ? x1 : 0.0f;
        out[g] = x1 + red[t][0] + bf2[0];
    }
}

// ---------------- launch ----------------
extern "C" void kernel_launch(void* const* d_in, const int* in_sizes, int n_in,
                              void* d_out, int out_size) {
    const float* x       = (const float*)d_in[0];
    const int*   ei      = (const int*)d_in[1];
    const int*   batch   = (const int*)d_in[2];
    const float* feature = (const float*)d_in[3];
    const float* W1 = (const float*)d_in[4];
    const float* b1 = (const float*)d_in[5];
    const float* W2 = (const float*)d_in[6];
    const float* b2 = (const float*)d_in[7];
    const float* W3 = (const float*)d_in[8];
    const float* b3 = (const float*)d_in[9];
    const float* Wg = (const float*)d_in[10];
    const float* bg = (const float*)d_in[11];
    const float* Wf1 = (const float*)d_in[12];
    const float* bf1 = (const float*)d_in[13];
    const float* Wf2 = (const float*)d_in[14];
    const float* bf2 = (const float*)d_in[15];
    float* out = (float*)d_out;

    int N = in_sizes[0] / FF;
    int E = in_sizes[1] / 2;
    if (N > NMAX) N = NMAX;
    if (E > EMAX) E = EMAX;

    const int T = 256;
    int nb_E = (E + T - 1) / T;
    int nb_W = (N * 32 + T - 1) / T;   // warp-per-node kernels (8 nodes/block)

    hist_k<<<nb_E, T>>>(ei, E);
    scan_k<<<1, 1024>>>(N);            // dinv + zeroes g_cur/g_cnt/g_pool
    scatter_k<<<nb_E, T>>>(ei, E);

    // Layer 1 (44->44): aggregate raw x FIRST (S x), then transform (+b1,ReLU)
    //   relu(S(x W1) + b1) == relu((S x) W1 + b1)
    spmm_k<FF, false><<<nb_W, T>>>(x, nullptr, g_bufB, N);
    gemm_k<44, 44, true><<<nb_W, T>>>(g_bufB, LD44, W1, b1, g_bufC, LD44, N);
    // Layer 2 (44->88): aggregate at width 44 fused with transform (+b2, ReLU)
    spmm_gemm_k<<<nb_W, T>>>(g_bufC, W2, b2, g_bufA, N);
    // Layer 3 (88->44): transform first (narrower output), then aggregate
    // fused with global max pooling (+b3, ReLU inside)
    gemm_k<88, 44, false><<<nb_W, T>>>(g_bufA, 88, W3, nullptr, g_bufB, LD44, N);
    spmm_pool_k<<<nb_W, T>>>(g_bufB, b3, batch, N);

    final_k<<<GG / 8, 128>>>(feature, Wf1, bf1, Wf2, bf2, Wg, bg, out);
}

// round 9
// speedup vs baseline: 7.0821x; 5.0795x over previous
#include <cuda_runtime.h>

// Problem constants (shapes fixed by the dataset)
#define NMAX 100000
#define EMAX 1000000
constexpr int GG   = 1024;
constexpr int FF   = 44;
constexpr int LD44 = 48;   // padded stride for width-44 buffers
constexpr int FEAT = 1019;

constexpr int NB   = 296;  // 2 blocks/SM on >=148 SMs -- all resident
constexpr int TPB  = 512;  // 16 warps/block

// ---------------- scratch (no allocations allowed) ----------------
// Replay determinism: g_cnt/g_cur re-zeroed in phase 2c AFTER their last
// read, so each replay's phase 1/3 sees zeros (first call: zeroed at load).
// g_pool zeroed in 2c before phase 8. Barrier count self-resets each use.
__device__ int      g_cnt[NMAX];
__device__ int      g_rowptr[NMAX + 1];
__device__ int      g_cur[NMAX];
__device__ float    g_dinv[NMAX];
__device__ int      g_csrc[EMAX];
__device__ float    g_cw[EMAX];
__device__ float    g_bufA[(size_t)NMAX * 88];
__device__ float    g_bufB[(size_t)NMAX * LD44];
__device__ float    g_bufC[(size_t)NMAX * LD44];
__device__ float    g_pool[GG * FF];
__device__ int      g_bsum[1024];
__device__ unsigned g_barcnt = 0;
__device__ unsigned g_bargen = 0;

// ---------------- software grid barrier ----------------
// Safe because all NB blocks are simultaneously resident (see launch_bounds
// + smem budget). threadfence before: publish our writes; threadfence after:
// gpu-scope fence invalidates stale L1 before reading other blocks' output.
__device__ __forceinline__ void gridbar() {
    __threadfence();
    __syncthreads();
    if (threadIdx.x == 0) {
        unsigned gen = *((volatile unsigned*)&g_bargen);
        if (atomicAdd(&g_barcnt, 1u) == (unsigned)gridDim.x - 1u) {
            g_barcnt = 0;
            __threadfence();
            atomicExch(&g_bargen, gen + 1u);
        } else {
            while (*((volatile unsigned*)&g_bargen) == gen) { }
        }
    }
    __syncthreads();
    __threadfence();
}

// ---------------- SpMM core: warp computes one dst row (width 44) --------
template <int LDI>
__device__ __forceinline__ void spmm_row(const float* __restrict__ hw, int node,
                                         int lane, float& acc0, float& acc1) {
    float dii = g_dinv[node];
    float sw = dii * dii;
    int f1 = lane + 32;
    bool two = f1 < FF;
    acc0 = hw[(size_t)node * LDI + lane] * sw;                  // self-loop
    acc1 = two ? hw[(size_t)node * LDI + f1] * sw : 0.0f;
    int beg = g_rowptr[node];
    int end = g_rowptr[node + 1];
    for (int base = beg; base < end; base += 32) {
        int e = base + lane;
        int s = 0;
        float w = 0.0f;
        if (e < end) { s = g_csrc[e]; w = g_cw[e]; }
        int m = end - base;
#pragma unroll
        for (int j = 0; j < 32; j++) {
            if (j < m) {
                int ss = __shfl_sync(0xffffffffu, s, j);
                float ww = __shfl_sync(0xffffffffu, w, j);
                const float* row = hw + (size_t)ss * LDI;
                acc0 += ww * row[lane];
                if (two) acc1 += ww * row[f1];
            }
        }
    }
}

// ---------------- the whole pipeline in ONE launch ----------------
__global__ __launch_bounds__(TPB, 2)
void mega_k(const float* __restrict__ x, const int* __restrict__ ei,
            const int* __restrict__ batch, const float* __restrict__ feature,
            const float* __restrict__ W1, const float* __restrict__ b1,
            const float* __restrict__ W2, const float* __restrict__ b2,
            const float* __restrict__ W3, const float* __restrict__ b3,
            const float* __restrict__ Wg, const float* __restrict__ bg,
            const float* __restrict__ Wf1, const float* __restrict__ bf1,
            const float* __restrict__ Wf2, const float* __restrict__ bf2,
            float* __restrict__ out, int N, int E)
{
    __shared__ float sf[9216];          // 36KB, aliased per phase
    int* si = (int*)sf;

    const int tid  = threadIdx.x;
    const int b    = blockIdx.x;
    const int nb   = gridDim.x;
    const int nthr = nb * TPB;
    const int gtid = b * TPB + tid;
    const int wid  = tid >> 5, lane = tid & 31;
    const int gw   = b * 16 + wid;
    const int nwarps = nb * 16;

    // ---- phase 1: in-degree histogram over dst (g_cnt starts zeroed) ----
    for (int e = gtid; e < E; e += nthr)
        atomicAdd(&g_cnt[ei[E + e]], 1);          // no return -> REDG (L2)
    gridbar();

    // ---- phase 2a: per-thread chunk: read cnt, dinv, block-local scan ----
    int ck = (N + nthr - 1) / nthr;               // items per thread (any nb)
    int i0 = gtid * ck;
    int i1 = min(N, i0 + ck);
    int mysum = 0;
    for (int i = i0; i < i1; i++) {
        int c = g_cnt[i];
        g_dinv[i] = rsqrtf((float)(c + 1));       // +1 self-loop
        mysum += c;
    }
    si[tid] = mysum;
    __syncthreads();
    for (int off = 1; off < TPB; off <<= 1) {
        int v = (tid >= off) ? si[tid - off] : 0;
        __syncthreads();
        si[tid] += v;
        __syncthreads();
    }
    int myexcl = si[tid] - mysum;                 // exclusive prefix within block
    if (tid == TPB - 1) g_bsum[b] = si[TPB - 1];  // block total
    gridbar();

    // ---- phase 2b: block 0 scans the per-block totals (nb <= TPB) ----
    if (b == 0) {
        int v = (tid < nb) ? g_bsum[tid] : 0;
        si[tid] = v;
        __syncthreads();
        for (int off = 1; off < TPB; off <<= 1) {
            int u = (tid >= off) ? si[tid - off] : 0;
            __syncthreads();
            si[tid] += u;
            __syncthreads();
        }
        if (tid < nb) g_bsum[tid] = si[tid] - v;  // exclusive
        if (tid == nb - 1) g_rowptr[N] = si[tid]; // total edge count
    }
    gridbar();

    // ---- phase 2c: rowptr; zero cnt/cur (for scatter + next replay); pool
    {
        int off = g_bsum[b] + myexcl;
        for (int i = i0; i < i1; i++) {
            g_rowptr[i] = off;
            off += g_cnt[i];
            g_cnt[i] = 0;
            g_cur[i] = 0;
        }
        for (int i = gtid; i < GG * FF; i += nthr) g_pool[i] = 0.0f;
    }
    gridbar();

    // ---- phase 3: scatter edges into CSR ----
    for (int e = gtid; e < E; e += nthr) {
        int s = ei[e];
        int d = ei[E + e];
        int p = atomicAdd(&g_cur[d], 1);
        int idx = g_rowptr[d] + p;
        g_csrc[idx] = s;
        g_cw[idx] = g_dinv[s] * g_dinv[d];
    }
    gridbar();

    // contiguous row range per warp for all node phases
    int R  = (N + nwarps - 1) / nwarps;
    int r0 = gw * R;
    int r1 = min(N, r0 + R);

    // ---- phase 4: layer-1 aggregation over raw x (S x) ----
    for (int row = r0; row < r1; row++) {
        float a0, a1;
        spmm_row<FF>(x, row, lane, a0, a1);
        g_bufB[(size_t)row * LD44 + lane] = a0;
        if (lane < 12) g_bufB[(size_t)row * LD44 + lane + 32] = a1;
    }
    gridbar();

    // ---- phase 5: (S x) @ W1 + b1, ReLU  (44->44) ----
    for (int i = tid; i < 44 * 44; i += TPB) sf[i] = W1[i];
    __syncthreads();
    for (int row = r0; row < r1; row++) {
        float h0 = g_bufB[(size_t)row * LD44 + lane];
        float h1 = (lane < 12) ? g_bufB[(size_t)row * LD44 + lane + 32] : 0.0f;
        float a0 = 0.0f, a1 = 0.0f;
#pragma unroll
        for (int k = 0; k < 44; k++) {
            float hk = __shfl_sync(0xffffffffu, (k < 32) ? h0 : h1, k & 31);
            a0 += hk * sf[k * 44 + lane];
            if (lane < 12) a1 += hk * sf[k * 44 + lane + 32];
        }
        a0 += __ldg(&b1[lane]);
        g_bufC[(size_t)row * LD44 + lane] = a0 > 0.0f ? a0 : 0.0f;
        if (lane < 12) {
            a1 += __ldg(&b1[lane + 32]);
            g_bufC[(size_t)row * LD44 + lane + 32] = a1 > 0.0f ? a1 : 0.0f;
        }
    }
    gridbar();

    // ---- phase 6: (S h1) @ W2 + b2, ReLU  (44->88, aggregation fused) ----
    for (int i = tid; i < 44 * 88; i += TPB) sf[i] = W2[i];
    __syncthreads();
    for (int row = r0; row < r1; row++) {
        float h0, h1;
        spmm_row<LD44>(g_bufC, row, lane, h0, h1);
        float o0 = 0.0f, o1 = 0.0f, o2 = 0.0f;
        bool t2 = lane < 24;
#pragma unroll
        for (int k = 0; k < 44; k++) {
            float hk = __shfl_sync(0xffffffffu, (k < 32) ? h0 : h1, k & 31);
            const float* wr = sf + k * 88;
            o0 += hk * wr[lane];
            o1 += hk * wr[lane + 32];
            if (t2) o2 += hk * wr[lane + 64];
        }
        float* orow = g_bufA + (size_t)row * 88;
        o0 += __ldg(&b2[lane]);
        orow[lane] = o0 > 0.0f ? o0 : 0.0f;
        o1 += __ldg(&b2[lane + 32]);
        orow[lane + 32] = o1 > 0.0f ? o1 : 0.0f;
        if (t2) {
            o2 += __ldg(&b2[lane + 64]);
            orow[lane + 64] = o2 > 0.0f ? o2 : 0.0f;
        }
    }
    gridbar();

    // ---- phase 7: h2 @ W3  (88->44, no bias yet) ----
    for (int i = tid; i < 88 * 44; i += TPB) sf[i] = W3[i];
    __syncthreads();
    for (int row = r0; row < r1; row++) {
        const float* hrow = g_bufA + (size_t)row * 88;
        float h0 = hrow[lane];
        float h1 = hrow[lane + 32];
        float h2 = (lane < 24) ? hrow[lane + 64] : 0.0f;
        float a0 = 0.0f, a1 = 0.0f;
#pragma unroll
        for (int k = 0; k < 88; k++) {
            float src = (k < 32) ? h0 : ((k < 64) ? h1 : h2);
            float hk = __shfl_sync(0xffffffffu, src, k & 31);
            a0 += hk * sf[k * 44 + lane];
            if (lane < 12) a1 += hk * sf[k * 44 + lane + 32];
        }
        g_bufB[(size_t)row * LD44 + lane] = a0;
        if (lane < 12) g_bufB[(size_t)row * LD44 + lane + 32] = a1;
    }
    gridbar();

    // ---- phase 8: layer-3 aggregation (+b3, ReLU) fused with max pool ----
    // Contiguous rows per warp + sorted batch -> run-max, few atomics.
    {
        float m0 = 0.0f, m1 = 0.0f;
        int curg = -1;
        for (int row = r0; row < r1; row++) {
            float a0, a1;
            spmm_row<LD44>(g_bufB, row, lane, a0, a1);
            a0 += __ldg(&b3[lane]);
            a0 = a0 > 0.0f ? a0 : 0.0f;
            if (lane < 12) {
                a1 += __ldg(&b3[lane + 32]);
                a1 = a1 > 0.0f ? a1 : 0.0f;
            }
            int g = batch[row];                    // uniform across warp
            if (g != curg) {
                if (curg >= 0) {
                    atomicMax((int*)&g_pool[curg * FF + lane], __float_as_int(m0));
                    if (lane < 12)
                        atomicMax((int*)&g_pool[curg * FF + lane + 32], __float_as_int(m1));
                }
                m0 = 0.0f; m1 = 0.0f;
                curg = g;
            }
            m0 = fmaxf(m0, a0);
            if (lane < 12) m1 = fmaxf(m1, a1);
        }
        if (curg >= 0) {
            atomicMax((int*)&g_pool[curg * FF + lane], __float_as_int(m0));
            if (lane < 12)
                atomicMax((int*)&g_pool[curg * FF + lane + 32], __float_as_int(m1));
        }
    }
    gridbar();

    // ---- phase 9: fused head (x1 + x2) ----
    // blocks 0..127: 8 graphs each; 4 thread-groups x 128, 2 graphs/group.
    if (b < GG / 8) {
        int g0 = b * 8;
        float* fsh = sf;            // 8*1019 floats
        float* red = sf + 8 * FEAT; // 8*128 floats
        for (int k = tid; k < 8 * FEAT; k += TPB)
            fsh[k] = feature[(size_t)g0 * FEAT + k];
        __syncthreads();
        int u  = tid & 127;
        int gg = tid >> 7;          // 0..3
        int ga = gg * 2, gb2 = gg * 2 + 1;
        float bb = bf1[u];
        float acc0 = bb, acc1 = bb;
        const float* fa = fsh + ga * FEAT;
        const float* fb = fsh + gb2 * FEAT;
#pragma unroll 4
        for (int k = 0; k < FEAT; k++) {
            float w = Wf1[k * 128 + u];
            acc0 += fa[k] * w;
            acc1 += fb[k] * w;
        }
        float w2 = Wf2[u];
        red[ga * 128 + u]  = (acc0 > 0.0f ? acc0 : 0.0f) * w2;
        red[gb2 * 128 + u] = (acc1 > 0.0f ? acc1 : 0.0f) * w2;
        __syncthreads();
        for (int sft = 64; sft >= 1; sft >>= 1) {
            if (u < sft) {
                red[ga * 128 + u]  += red[ga * 128 + u + sft];
                red[gb2 * 128 + u] += red[gb2 * 128 + u + sft];
            }
            __syncthreads();
        }
        if (tid < 8) {
            int g = g0 + tid;
            float x1 = bg[0];
            for (int k = 0; k < FF; k++) x1 += g_pool[g * FF + k] * Wg[k];
            x1 = x1 > 0.0f ? x1 : 0.0f;
            out[g] = x1 + red[tid * 128] + bf2[0];
        }
    }
}

// ---------------- launch: exactly ONE kernel ----------------
extern "C" void kernel_launch(void* const* d_in, const int* in_sizes, int n_in,
                              void* d_out, int out_size) {
    const float* x       = (const float*)d_in[0];
    const int*   ei      = (const int*)d_in[1];
    const int*   batch   = (const int*)d_in[2];
    const float* feature = (const float*)d_in[3];
    const float* W1 = (const float*)d_in[4];
    const float* b1 = (const float*)d_in[5];
    const float* W2 = (const float*)d_in[6];
    const float* b2 = (const float*)d_in[7];
    const float* W3 = (const float*)d_in[8];
    const float* b3 = (const float*)d_in[9];
    const float* Wg = (const float*)d_in[10];
    const float* bg = (const float*)d_in[11];
    const float* Wf1 = (const float*)d_in[12];
    const float* bf1 = (const float*)d_in[13];
    const float* Wf2 = (const float*)d_in[14];
    const float* bf2 = (const float*)d_in[15];
    float* out = (float*)d_out;

    int N = in_sizes[0] / FF;
    int E = in_sizes[1] / 2;
    if (N > NMAX) N = NMAX;
    if (E > EMAX) E = EMAX;

    mega_k<<<NB, TPB>>>(x, ei, batch, feature, W1, b1, W2, b2, W3, b3,
                        Wg, bg, Wf1, bf1, Wf2, bf2, out, N, E);
}